// round 13
// baseline (speedup 1.0000x reference)
#include <cuda_runtime.h>
#include <cstdint>

#define NNODES 5000000
#define NGRAPHS 100000
#define NODES_PER_GRAPH 50

// L2-resident scratch (60 MB total). g_deg is zero-initialized at load and
// re-zeroed by k_fc at the end of every run (deterministic across replays).
__device__ int   g_deg[NNODES];  // edge count (self loop added as +1 at use sites)
__device__ float g_p[NNODES];    // phase1: x*w ; phase2 onward: x*w*dis
__device__ float g_acc[NNODES];  // running scatter sum (init = p[i] == self-loop term)

// Per-thread dtype detect: int64 indices < 2^31 have all-zero high words.
__device__ __forceinline__ int detect_is64(const unsigned long long* e)
{
    ulonglong2 a = *reinterpret_cast<const ulonglong2*>(e);
    ulonglong2 b = *reinterpret_cast<const ulonglong2*>(e + 2);
    return ((a.x >> 32) | (a.y >> 32) | (b.x >> 32) | (b.y >> 32)) == 0ull;
}

// ---------------------------------------------------------------------------
// 1) degree count: RED.ADD to g_deg[col]. 4 edges/thread. (At L2-slice floor.)
//    First NNODES/4 threads also stream xw = x*conv_w into g_p (free DRAM work).
__global__ void __launch_bounds__(256, 8)
k_count(const long long* __restrict__ col64,
        const int* __restrict__ col32,
        const unsigned long long* __restrict__ ebase,
        const float* __restrict__ x,
        const float* __restrict__ conv_w, long long E)
{
    long long t    = (long long)blockIdx.x * blockDim.x + threadIdx.x;
    long long base = t * 4;
    if (detect_is64(ebase)) {
        if (base + 3 < E) {
            longlong2 a = *reinterpret_cast<const longlong2*>(col64 + base);
            longlong2 b = *reinterpret_cast<const longlong2*>(col64 + base + 2);
            atomicAdd(&g_deg[(int)a.x], 1);
            atomicAdd(&g_deg[(int)a.y], 1);
            atomicAdd(&g_deg[(int)b.x], 1);
            atomicAdd(&g_deg[(int)b.y], 1);
        } else {
            for (long long j = base; j < E; ++j)
                atomicAdd(&g_deg[(int)col64[j]], 1);
        }
    } else {
        if (base + 3 < E) {
            int4 c = *reinterpret_cast<const int4*>(col32 + base);
            atomicAdd(&g_deg[c.x], 1);
            atomicAdd(&g_deg[c.y], 1);
            atomicAdd(&g_deg[c.z], 1);
            atomicAdd(&g_deg[c.w], 1);
        } else {
            for (long long j = base; j < E; ++j)
                atomicAdd(&g_deg[col32[j]], 1);
        }
    }
    if (t < NNODES / 4) {
        float w = conv_w[0];
        float4 xv = reinterpret_cast<const float4*>(x)[t];
        xv.x *= w; xv.y *= w; xv.z *= w; xv.w *= w;
        reinterpret_cast<float4*>(g_p)[t] = xv;
    }
}

// ---------------------------------------------------------------------------
// 2) per-node prep (PDL follower): p = xw * rsqrt(deg+1); acc = p.
__global__ void k_prep()
{
    int i = blockIdx.x * blockDim.x + threadIdx.x;  // quad index
    const int n4 = NNODES / 4;                       // 1,250,000 (exact)
    cudaGridDependencySynchronize();                 // wait k_count writes
    if (i >= n4) return;
    int4   d  = reinterpret_cast<const int4*>(g_deg)[i];
    float4 xw = reinterpret_cast<const float4*>(g_p)[i];
    float4 p;
    p.x = xw.x * rsqrtf((float)(d.x + 1));
    p.y = xw.y * rsqrtf((float)(d.y + 1));
    p.z = xw.z * rsqrtf((float)(d.z + 1));
    p.w = xw.w * rsqrtf((float)(d.w + 1));
    reinterpret_cast<float4*>(g_p)[i]   = p;
    reinterpret_cast<float4*>(g_acc)[i] = p;
}

// ---------------------------------------------------------------------------
// 3) edge scatter (PDL follower): acc[col] += p[row].
//    Edge-index loads issued BEFORE the dependency sync (upstream-independent).
__global__ void __launch_bounds__(256, 8)
k_edge(const long long* __restrict__ row64,
       const long long* __restrict__ col64,
       const int* __restrict__ row32,
       const int* __restrict__ col32,
       const unsigned long long* __restrict__ ebase, long long E)
{
    long long t    = (long long)blockIdx.x * blockDim.x + threadIdx.x;
    long long base = t * 4;
    if (detect_is64(ebase)) {
        if (base + 3 < E) {
            longlong2 r0 = *reinterpret_cast<const longlong2*>(row64 + base);
            longlong2 r1 = *reinterpret_cast<const longlong2*>(row64 + base + 2);
            longlong2 c0 = *reinterpret_cast<const longlong2*>(col64 + base);
            longlong2 c1 = *reinterpret_cast<const longlong2*>(col64 + base + 2);
            cudaGridDependencySynchronize();         // wait k_prep (g_p, g_acc)
            float p0 = __ldg(&g_p[(int)r0.x]);
            float p1 = __ldg(&g_p[(int)r0.y]);
            float p2 = __ldg(&g_p[(int)r1.x]);
            float p3 = __ldg(&g_p[(int)r1.y]);
            atomicAdd(&g_acc[(int)c0.x], p0);
            atomicAdd(&g_acc[(int)c0.y], p1);
            atomicAdd(&g_acc[(int)c1.x], p2);
            atomicAdd(&g_acc[(int)c1.y], p3);
        } else {
            cudaGridDependencySynchronize();
            for (long long j = base; j < E; ++j)
                atomicAdd(&g_acc[(int)col64[j]], __ldg(&g_p[(int)row64[j]]));
        }
    } else {
        if (base + 3 < E) {
            int4 r = *reinterpret_cast<const int4*>(row32 + base);
            int4 c = *reinterpret_cast<const int4*>(col32 + base);
            cudaGridDependencySynchronize();         // wait k_prep (g_p, g_acc)
            float p0 = __ldg(&g_p[r.x]);
            float p1 = __ldg(&g_p[r.y]);
            float p2 = __ldg(&g_p[r.z]);
            float p3 = __ldg(&g_p[r.w]);
            atomicAdd(&g_acc[c.x], p0);
            atomicAdd(&g_acc[c.y], p1);
            atomicAdd(&g_acc[c.z], p2);
            atomicAdd(&g_acc[c.w], p3);
        } else {
            cudaGridDependencySynchronize();
            for (long long j = base; j < E; ++j)
                atomicAdd(&g_acc[col32[j]], __ldg(&g_p[row32[j]]));
        }
    }
}

// ---------------------------------------------------------------------------
// 4) fused h + FC, spill-free: one thread per TWO graphs (100 nodes), h values
//    consumed immediately (no staging array). Graph/weight selection per node
//    index is compile-time (fully unrolled). Re-zeros g_deg range for replay.
__global__ void k_fc(const float* __restrict__ conv_b,
                     const float* __restrict__ fc_w,   // [2,50] row-major
                     const float* __restrict__ fc_b,   // [2]
                     float* __restrict__ out)          // [NGRAPHS,2]
{
    int t = blockIdx.x * blockDim.x + threadIdx.x;     // graph pair index
    const int npairs = NGRAPHS / 2;                    // 50,000
    cudaGridDependencySynchronize();                   // wait k_edge (g_acc)
    if (t >= npairs) return;
    float b   = conv_b[0];
    float s00 = fc_b[0], s01 = fc_b[1];
    float s10 = s00,     s11 = s01;
    int base = t * 2 * NODES_PER_GRAPH;                // multiple of 4

#pragma unroll
    for (int q = 0; q < 25; ++q) {
        int4   d = reinterpret_cast<const int4*>(g_deg + base)[q];
        float4 a = reinterpret_cast<const float4*>(g_acc + base)[q];
        reinterpret_cast<int4*>(g_deg + base)[q] = make_int4(0, 0, 0, 0);
        float hv[4];
        hv[0] = rsqrtf((float)(d.x + 1)) * a.x + b;
        hv[1] = rsqrtf((float)(d.y + 1)) * a.y + b;
        hv[2] = rsqrtf((float)(d.z + 1)) * a.z + b;
        hv[3] = rsqrtf((float)(d.w + 1)) * a.w + b;
#pragma unroll
        for (int u = 0; u < 4; ++u) {
            const int n = 4 * q + u;                   // compile-time constant
            if (n < NODES_PER_GRAPH) {
                float w0 = __ldg(&fc_w[n]);
                float w1 = __ldg(&fc_w[NODES_PER_GRAPH + n]);
                s00 = fmaf(hv[u], w0, s00);
                s01 = fmaf(hv[u], w1, s01);
            } else {
                float w0 = __ldg(&fc_w[n - NODES_PER_GRAPH]);
                float w1 = __ldg(&fc_w[n]);
                s10 = fmaf(hv[u], w0, s10);
                s11 = fmaf(hv[u], w1, s11);
            }
        }
    }
    reinterpret_cast<float4*>(out)[t] = make_float4(s00, s01, s10, s11);
}

// ---------------------------------------------------------------------------
static void launch_pdl(void* func, dim3 grid, dim3 block,
                       void** args, bool pdl)
{
    cudaLaunchConfig_t cfg = {};
    cfg.gridDim  = grid;
    cfg.blockDim = block;
    cfg.stream   = 0;
    cudaLaunchAttribute attr[1];
    if (pdl) {
        attr[0].id = cudaLaunchAttributeProgrammaticStreamSerialization;
        attr[0].val.programmaticStreamSerializationAllowed = 1;
        cfg.attrs = attr;
        cfg.numAttrs = 1;
    }
    cudaLaunchKernelExC(&cfg, func, args);
}

extern "C" void kernel_launch(void* const* d_in, const int* in_sizes, int n_in,
                              void* d_out, int out_size)
{
    // Resolve inputs BY SIZE. Sizes: x=5,000,000; edge_index=160,000,000
    // (elements, dtype int32 or int64 — detected on device);
    // conv_w=1; conv_b=1 (in appearance order); fc_w=100; fc_b=2.
    const float* x      = nullptr;
    const void*  eidx   = nullptr;
    const float* conv_w = nullptr;
    const float* conv_b = nullptr;
    const float* fc_w   = nullptr;
    const float* fc_b   = nullptr;
    long long    n_edge_elems = 0;

    for (int i = 0; i < n_in; ++i) {
        long long s = in_sizes[i];
        if (s == 160000000LL)      { eidx = d_in[i]; n_edge_elems = s; }
        else if (s == 5000000LL)   { x    = (const float*)d_in[i]; }
        else if (s == 100LL)       { fc_w = (const float*)d_in[i]; }
        else if (s == 2LL)         { fc_b = (const float*)d_in[i]; }
        else if (s == 1LL) {
            if (!conv_w) conv_w = (const float*)d_in[i];
            else         conv_b = (const float*)d_in[i];
        }
    }

    float* out = (float*)d_out;
    long long E = n_edge_elems / 2;

    const long long* row64 = (const long long*)eidx;
    const long long* col64 = row64 + E;
    const int*       row32 = (const int*)eidx;
    const int*       col32 = row32 + E;
    const unsigned long long* ebase = (const unsigned long long*)eidx;

    const int TPB = 256;
    dim3 blk(TPB);
    dim3 prep_grid((NNODES / 4 + TPB - 1) / TPB);
    dim3 edge_grid((unsigned)((E + (long long)TPB * 4 - 1) / ((long long)TPB * 4)));
    dim3 fc_grid((NGRAPHS / 2 + TPB - 1) / TPB);

    {   // k_count (no PDL — first kernel; g_deg zeroed by prior k_fc / load-init)
        void* args[] = {(void*)&col64, (void*)&col32, (void*)&ebase,
                        (void*)&x, (void*)&conv_w, (void*)&E};
        launch_pdl((void*)k_count, edge_grid, blk, args, false);
    }
    {   // k_prep (PDL)
        void* args[] = {};
        launch_pdl((void*)k_prep, prep_grid, blk, args, true);
    }
    {   // k_edge (PDL)
        void* args[] = {(void*)&row64, (void*)&col64, (void*)&row32,
                        (void*)&col32, (void*)&ebase, (void*)&E};
        launch_pdl((void*)k_edge, edge_grid, blk, args, true);
    }
    {   // k_fc (PDL)
        void* args[] = {(void*)&conv_b, (void*)&fc_w, (void*)&fc_b, (void*)&out};
        launch_pdl((void*)k_fc, fc_grid, blk, args, true);
    }
}

// round 15
// speedup vs baseline: 1.0931x; 1.0931x over previous
#include <cuda_runtime.h>
#include <cstdint>

#define NNODES 5000000
#define NGRAPHS 100000
#define NODES_PER_GRAPH 50
#define FC_GRAPHS_PER_BLOCK 100              // 5000 nodes, 20 KB smem
#define FC_NODES_PER_BLOCK (FC_GRAPHS_PER_BLOCK * NODES_PER_GRAPH)

// L2-resident scratch (60 MB total). g_deg is zero-initialized at load and
// re-zeroed by k_fc at the end of every run (deterministic across replays).
__device__ int   g_deg[NNODES];  // edge count (self loop added as +1 at use sites)
__device__ float g_p[NNODES];    // phase1: x*w ; phase2 onward: x*w*dis
__device__ float g_acc[NNODES];  // running scatter sum (init = p[i] == self-loop term)

// Per-thread dtype detect: int64 indices < 2^31 have all-zero high words.
__device__ __forceinline__ int detect_is64(const unsigned long long* e)
{
    ulonglong2 a = *reinterpret_cast<const ulonglong2*>(e);
    ulonglong2 b = *reinterpret_cast<const ulonglong2*>(e + 2);
    return ((a.x >> 32) | (a.y >> 32) | (b.x >> 32) | (b.y >> 32)) == 0ull;
}

// ---------------------------------------------------------------------------
// 1) degree count: RED.ADD to g_deg[col]. 4 edges/thread. (At L2-slice floor.)
//    First NNODES/4 threads also stream xw = x*conv_w into g_p (free DRAM work).
__global__ void __launch_bounds__(256, 8)
k_count(const long long* __restrict__ col64,
        const int* __restrict__ col32,
        const unsigned long long* __restrict__ ebase,
        const float* __restrict__ x,
        const float* __restrict__ conv_w, long long E)
{
    long long t    = (long long)blockIdx.x * blockDim.x + threadIdx.x;
    long long base = t * 4;
    if (detect_is64(ebase)) {
        if (base + 3 < E) {
            longlong2 a = *reinterpret_cast<const longlong2*>(col64 + base);
            longlong2 b = *reinterpret_cast<const longlong2*>(col64 + base + 2);
            atomicAdd(&g_deg[(int)a.x], 1);
            atomicAdd(&g_deg[(int)a.y], 1);
            atomicAdd(&g_deg[(int)b.x], 1);
            atomicAdd(&g_deg[(int)b.y], 1);
        } else {
            for (long long j = base; j < E; ++j)
                atomicAdd(&g_deg[(int)col64[j]], 1);
        }
    } else {
        if (base + 3 < E) {
            int4 c = *reinterpret_cast<const int4*>(col32 + base);
            atomicAdd(&g_deg[c.x], 1);
            atomicAdd(&g_deg[c.y], 1);
            atomicAdd(&g_deg[c.z], 1);
            atomicAdd(&g_deg[c.w], 1);
        } else {
            for (long long j = base; j < E; ++j)
                atomicAdd(&g_deg[col32[j]], 1);
        }
    }
    if (t < NNODES / 4) {
        float w = conv_w[0];
        float4 xv = reinterpret_cast<const float4*>(x)[t];
        xv.x *= w; xv.y *= w; xv.z *= w; xv.w *= w;
        reinterpret_cast<float4*>(g_p)[t] = xv;
    }
}

// ---------------------------------------------------------------------------
// 2) per-node prep (PDL follower): p = xw * rsqrt(deg+1); acc = p.
__global__ void k_prep()
{
    int i = blockIdx.x * blockDim.x + threadIdx.x;  // quad index
    const int n4 = NNODES / 4;                       // 1,250,000 (exact)
    cudaGridDependencySynchronize();                 // wait k_count writes
    if (i >= n4) return;
    int4   d  = reinterpret_cast<const int4*>(g_deg)[i];
    float4 xw = reinterpret_cast<const float4*>(g_p)[i];
    float4 p;
    p.x = xw.x * rsqrtf((float)(d.x + 1));
    p.y = xw.y * rsqrtf((float)(d.y + 1));
    p.z = xw.z * rsqrtf((float)(d.z + 1));
    p.w = xw.w * rsqrtf((float)(d.w + 1));
    reinterpret_cast<float4*>(g_p)[i]   = p;
    reinterpret_cast<float4*>(g_acc)[i] = p;
}

// ---------------------------------------------------------------------------
// 3) edge scatter (PDL follower): acc[col] += p[row].
//    Edge-index loads issued BEFORE the dependency sync (upstream-independent).
__global__ void __launch_bounds__(256, 8)
k_edge(const long long* __restrict__ row64,
       const long long* __restrict__ col64,
       const int* __restrict__ row32,
       const int* __restrict__ col32,
       const unsigned long long* __restrict__ ebase, long long E)
{
    long long t    = (long long)blockIdx.x * blockDim.x + threadIdx.x;
    long long base = t * 4;
    if (detect_is64(ebase)) {
        if (base + 3 < E) {
            longlong2 r0 = *reinterpret_cast<const longlong2*>(row64 + base);
            longlong2 r1 = *reinterpret_cast<const longlong2*>(row64 + base + 2);
            longlong2 c0 = *reinterpret_cast<const longlong2*>(col64 + base);
            longlong2 c1 = *reinterpret_cast<const longlong2*>(col64 + base + 2);
            cudaGridDependencySynchronize();         // wait k_prep (g_p, g_acc)
            float p0 = __ldg(&g_p[(int)r0.x]);
            float p1 = __ldg(&g_p[(int)r0.y]);
            float p2 = __ldg(&g_p[(int)r1.x]);
            float p3 = __ldg(&g_p[(int)r1.y]);
            atomicAdd(&g_acc[(int)c0.x], p0);
            atomicAdd(&g_acc[(int)c0.y], p1);
            atomicAdd(&g_acc[(int)c1.x], p2);
            atomicAdd(&g_acc[(int)c1.y], p3);
        } else {
            cudaGridDependencySynchronize();
            for (long long j = base; j < E; ++j)
                atomicAdd(&g_acc[(int)col64[j]], __ldg(&g_p[(int)row64[j]]));
        }
    } else {
        if (base + 3 < E) {
            int4 r = *reinterpret_cast<const int4*>(row32 + base);
            int4 c = *reinterpret_cast<const int4*>(col32 + base);
            cudaGridDependencySynchronize();         // wait k_prep (g_p, g_acc)
            float p0 = __ldg(&g_p[r.x]);
            float p1 = __ldg(&g_p[r.y]);
            float p2 = __ldg(&g_p[r.z]);
            float p3 = __ldg(&g_p[r.w]);
            atomicAdd(&g_acc[c.x], p0);
            atomicAdd(&g_acc[c.y], p1);
            atomicAdd(&g_acc[c.z], p2);
            atomicAdd(&g_acc[c.w], p3);
        } else {
            cudaGridDependencySynchronize();
            for (long long j = base; j < E; ++j)
                atomicAdd(&g_acc[col32[j]], __ldg(&g_p[row32[j]]));
        }
    }
}

// ---------------------------------------------------------------------------
// 4) block-cooperative FC epilogue (PDL follower).
//    Phase A (coalesced): h = rsqrt(deg+1)*acc + conv_b into smem; re-zero deg.
//    Phase B: 100 threads reduce one graph (50 smem values) each.
__global__ void __launch_bounds__(256, 4)
k_fc(const float* __restrict__ conv_b,
     const float* __restrict__ fc_w,   // [2,50] row-major
     const float* __restrict__ fc_b,   // [2]
     float* __restrict__ out)          // [NGRAPHS,2]
{
    __shared__ float sh[FC_NODES_PER_BLOCK];         // 5000 floats = 20 KB
    const int nbase = blockIdx.x * FC_NODES_PER_BLOCK;
    cudaGridDependencySynchronize();                 // wait k_edge (g_acc)
    float b = conv_b[0];

    // Phase A: 1250 quads, coalesced. Loads first, zero-stores after.
    const int NQ = FC_NODES_PER_BLOCK / 4;           // 1250
    for (int q = threadIdx.x; q < NQ; q += 256) {
        int4   d = reinterpret_cast<const int4*>(g_deg + nbase)[q];
        float4 a = reinterpret_cast<const float4*>(g_acc + nbase)[q];
        float4 h;
        h.x = rsqrtf((float)(d.x + 1)) * a.x + b;
        h.y = rsqrtf((float)(d.y + 1)) * a.y + b;
        h.z = rsqrtf((float)(d.z + 1)) * a.z + b;
        h.w = rsqrtf((float)(d.w + 1)) * a.w + b;
        reinterpret_cast<float4*>(sh)[q] = h;
    }
    // Re-zero this block's exclusive g_deg range (coalesced, outside load chain).
    for (int q = threadIdx.x; q < NQ; q += 256)
        reinterpret_cast<int4*>(g_deg + nbase)[q] = make_int4(0, 0, 0, 0);
    __syncthreads();

    // Phase B: one thread per graph.
    if (threadIdx.x < FC_GRAPHS_PER_BLOCK) {
        int g = blockIdx.x * FC_GRAPHS_PER_BLOCK + threadIdx.x;
        const float* hh = sh + threadIdx.x * NODES_PER_GRAPH;
        float s0 = fc_b[0];
        float s1 = fc_b[1];
#pragma unroll
        for (int j = 0; j < NODES_PER_GRAPH; ++j) {
            float h = hh[j];
            s0 = fmaf(h, __ldg(&fc_w[j]), s0);
            s1 = fmaf(h, __ldg(&fc_w[NODES_PER_GRAPH + j]), s1);
        }
        reinterpret_cast<float2*>(out)[g] = make_float2(s0, s1);
    }
}

// ---------------------------------------------------------------------------
static void launch_pdl(void* func, dim3 grid, dim3 block,
                       void** args, bool pdl)
{
    cudaLaunchConfig_t cfg = {};
    cfg.gridDim  = grid;
    cfg.blockDim = block;
    cfg.stream   = 0;
    cudaLaunchAttribute attr[1];
    if (pdl) {
        attr[0].id = cudaLaunchAttributeProgrammaticStreamSerialization;
        attr[0].val.programmaticStreamSerializationAllowed = 1;
        cfg.attrs = attr;
        cfg.numAttrs = 1;
    }
    cudaLaunchKernelExC(&cfg, func, args);
}

extern "C" void kernel_launch(void* const* d_in, const int* in_sizes, int n_in,
                              void* d_out, int out_size)
{
    // Resolve inputs BY SIZE. Sizes: x=5,000,000; edge_index=160,000,000
    // (elements, dtype int32 or int64 — detected on device);
    // conv_w=1; conv_b=1 (in appearance order); fc_w=100; fc_b=2.
    const float* x      = nullptr;
    const void*  eidx   = nullptr;
    const float* conv_w = nullptr;
    const float* conv_b = nullptr;
    const float* fc_w   = nullptr;
    const float* fc_b   = nullptr;
    long long    n_edge_elems = 0;

    for (int i = 0; i < n_in; ++i) {
        long long s = in_sizes[i];
        if (s == 160000000LL)      { eidx = d_in[i]; n_edge_elems = s; }
        else if (s == 5000000LL)   { x    = (const float*)d_in[i]; }
        else if (s == 100LL)       { fc_w = (const float*)d_in[i]; }
        else if (s == 2LL)         { fc_b = (const float*)d_in[i]; }
        else if (s == 1LL) {
            if (!conv_w) conv_w = (const float*)d_in[i];
            else         conv_b = (const float*)d_in[i];
        }
    }

    float* out = (float*)d_out;
    long long E = n_edge_elems / 2;

    const long long* row64 = (const long long*)eidx;
    const long long* col64 = row64 + E;
    const int*       row32 = (const int*)eidx;
    const int*       col32 = row32 + E;
    const unsigned long long* ebase = (const unsigned long long*)eidx;

    const int TPB = 256;
    dim3 blk(TPB);
    dim3 prep_grid((NNODES / 4 + TPB - 1) / TPB);
    dim3 edge_grid((unsigned)((E + (long long)TPB * 4 - 1) / ((long long)TPB * 4)));
    dim3 fc_grid(NGRAPHS / FC_GRAPHS_PER_BLOCK);     // 1000 (exact)

    {   // k_count (no PDL — first kernel; g_deg zeroed by prior k_fc / load-init)
        void* args[] = {(void*)&col64, (void*)&col32, (void*)&ebase,
                        (void*)&x, (void*)&conv_w, (void*)&E};
        launch_pdl((void*)k_count, edge_grid, blk, args, false);
    }
    {   // k_prep (PDL)
        void* args[] = {};
        launch_pdl((void*)k_prep, prep_grid, blk, args, true);
    }
    {   // k_edge (PDL)
        void* args[] = {(void*)&row64, (void*)&col64, (void*)&row32,
                        (void*)&col32, (void*)&ebase, (void*)&E};
        launch_pdl((void*)k_edge, edge_grid, blk, args, true);
    }
    {   // k_fc (PDL)
        void* args[] = {(void*)&conv_b, (void*)&fc_w, (void*)&fc_b, (void*)&out};
        launch_pdl((void*)k_fc, fc_grid, blk, args, true);
    }
}

// round 16
// speedup vs baseline: 1.0960x; 1.0027x over previous
#include <cuda_runtime.h>
#include <cstdint>

#define NNODES 5000000
#define NGRAPHS 100000
#define NODES_PER_GRAPH 50
#define FC_TPB 512
#define FC_GRAPHS_PER_BLOCK 100              // 5000 nodes, 20 KB smem
#define FC_NODES_PER_BLOCK (FC_GRAPHS_PER_BLOCK * NODES_PER_GRAPH)

// L2-resident scratch (60 MB total). g_deg is zero-initialized at load and
// re-zeroed by k_fc at the end of every run (deterministic across replays).
__device__ int   g_deg[NNODES];  // edge count (self loop added as +1 at use sites)
__device__ float g_p[NNODES];    // phase1: x*w ; phase2 onward: x*w*dis
__device__ float g_acc[NNODES];  // running scatter sum (init = p[i] == self-loop term)

// Per-thread dtype detect: int64 indices < 2^31 have all-zero high words.
__device__ __forceinline__ int detect_is64(const unsigned long long* e)
{
    ulonglong2 a = *reinterpret_cast<const ulonglong2*>(e);
    ulonglong2 b = *reinterpret_cast<const ulonglong2*>(e + 2);
    return ((a.x >> 32) | (a.y >> 32) | (b.x >> 32) | (b.y >> 32)) == 0ull;
}

// ---------------------------------------------------------------------------
// 1) degree count: RED.ADD to g_deg[col]. 4 edges/thread. (At L2-slice floor.)
//    First NNODES/4 threads also stream xw = x*conv_w into g_p (free DRAM work).
__global__ void __launch_bounds__(256, 8)
k_count(const long long* __restrict__ col64,
        const int* __restrict__ col32,
        const unsigned long long* __restrict__ ebase,
        const float* __restrict__ x,
        const float* __restrict__ conv_w, long long E)
{
    long long t    = (long long)blockIdx.x * blockDim.x + threadIdx.x;
    long long base = t * 4;
    if (detect_is64(ebase)) {
        if (base + 3 < E) {
            longlong2 a = *reinterpret_cast<const longlong2*>(col64 + base);
            longlong2 b = *reinterpret_cast<const longlong2*>(col64 + base + 2);
            atomicAdd(&g_deg[(int)a.x], 1);
            atomicAdd(&g_deg[(int)a.y], 1);
            atomicAdd(&g_deg[(int)b.x], 1);
            atomicAdd(&g_deg[(int)b.y], 1);
        } else {
            for (long long j = base; j < E; ++j)
                atomicAdd(&g_deg[(int)col64[j]], 1);
        }
    } else {
        if (base + 3 < E) {
            int4 c = *reinterpret_cast<const int4*>(col32 + base);
            atomicAdd(&g_deg[c.x], 1);
            atomicAdd(&g_deg[c.y], 1);
            atomicAdd(&g_deg[c.z], 1);
            atomicAdd(&g_deg[c.w], 1);
        } else {
            for (long long j = base; j < E; ++j)
                atomicAdd(&g_deg[col32[j]], 1);
        }
    }
    if (t < NNODES / 4) {
        float w = conv_w[0];
        float4 xv = reinterpret_cast<const float4*>(x)[t];
        xv.x *= w; xv.y *= w; xv.z *= w; xv.w *= w;
        reinterpret_cast<float4*>(g_p)[t] = xv;
    }
}

// ---------------------------------------------------------------------------
// 2) per-node prep (PDL follower): p = xw * rsqrt(deg+1); acc = p.
__global__ void __launch_bounds__(FC_TPB)
k_prep()
{
    int i = blockIdx.x * blockDim.x + threadIdx.x;  // quad index
    const int n4 = NNODES / 4;                       // 1,250,000 (exact)
    cudaGridDependencySynchronize();                 // wait k_count writes
    if (i >= n4) return;
    int4   d  = reinterpret_cast<const int4*>(g_deg)[i];
    float4 xw = reinterpret_cast<const float4*>(g_p)[i];
    float4 p;
    p.x = xw.x * rsqrtf((float)(d.x + 1));
    p.y = xw.y * rsqrtf((float)(d.y + 1));
    p.z = xw.z * rsqrtf((float)(d.z + 1));
    p.w = xw.w * rsqrtf((float)(d.w + 1));
    reinterpret_cast<float4*>(g_p)[i]   = p;
    reinterpret_cast<float4*>(g_acc)[i] = p;
}

// ---------------------------------------------------------------------------
// 3) edge scatter (PDL follower): acc[col] += p[row].
//    Edge-index loads issued BEFORE the dependency sync (upstream-independent).
__global__ void __launch_bounds__(256, 8)
k_edge(const long long* __restrict__ row64,
       const long long* __restrict__ col64,
       const int* __restrict__ row32,
       const int* __restrict__ col32,
       const unsigned long long* __restrict__ ebase, long long E)
{
    long long t    = (long long)blockIdx.x * blockDim.x + threadIdx.x;
    long long base = t * 4;
    if (detect_is64(ebase)) {
        if (base + 3 < E) {
            longlong2 r0 = *reinterpret_cast<const longlong2*>(row64 + base);
            longlong2 r1 = *reinterpret_cast<const longlong2*>(row64 + base + 2);
            longlong2 c0 = *reinterpret_cast<const longlong2*>(col64 + base);
            longlong2 c1 = *reinterpret_cast<const longlong2*>(col64 + base + 2);
            cudaGridDependencySynchronize();         // wait k_prep (g_p, g_acc)
            float p0 = __ldg(&g_p[(int)r0.x]);
            float p1 = __ldg(&g_p[(int)r0.y]);
            float p2 = __ldg(&g_p[(int)r1.x]);
            float p3 = __ldg(&g_p[(int)r1.y]);
            atomicAdd(&g_acc[(int)c0.x], p0);
            atomicAdd(&g_acc[(int)c0.y], p1);
            atomicAdd(&g_acc[(int)c1.x], p2);
            atomicAdd(&g_acc[(int)c1.y], p3);
        } else {
            cudaGridDependencySynchronize();
            for (long long j = base; j < E; ++j)
                atomicAdd(&g_acc[(int)col64[j]], __ldg(&g_p[(int)row64[j]]));
        }
    } else {
        if (base + 3 < E) {
            int4 r = *reinterpret_cast<const int4*>(row32 + base);
            int4 c = *reinterpret_cast<const int4*>(col32 + base);
            cudaGridDependencySynchronize();         // wait k_prep (g_p, g_acc)
            float p0 = __ldg(&g_p[r.x]);
            float p1 = __ldg(&g_p[r.y]);
            float p2 = __ldg(&g_p[r.z]);
            float p3 = __ldg(&g_p[r.w]);
            atomicAdd(&g_acc[c.x], p0);
            atomicAdd(&g_acc[c.y], p1);
            atomicAdd(&g_acc[c.z], p2);
            atomicAdd(&g_acc[c.w], p3);
        } else {
            cudaGridDependencySynchronize();
            for (long long j = base; j < E; ++j)
                atomicAdd(&g_acc[col32[j]], __ldg(&g_p[row32[j]]));
        }
    }
}

// ---------------------------------------------------------------------------
// 4) block-cooperative FC epilogue (PDL follower), 512 threads for full SM
//    occupancy on the Phase-A DRAM stream.
__global__ void __launch_bounds__(FC_TPB, 4)
k_fc(const float* __restrict__ conv_b,
     const float* __restrict__ fc_w,   // [2,50] row-major
     const float* __restrict__ fc_b,   // [2]
     float* __restrict__ out)          // [NGRAPHS,2]
{
    __shared__ float sh[FC_NODES_PER_BLOCK];         // 5000 floats = 20 KB
    const int nbase = blockIdx.x * FC_NODES_PER_BLOCK;
    cudaGridDependencySynchronize();                 // wait k_edge (g_acc)
    float b = conv_b[0];

    // Phase A: 1250 quads, coalesced. Loads first, zero-stores after.
    const int NQ = FC_NODES_PER_BLOCK / 4;           // 1250
    for (int q = threadIdx.x; q < NQ; q += FC_TPB) {
        int4   d = reinterpret_cast<const int4*>(g_deg + nbase)[q];
        float4 a = reinterpret_cast<const float4*>(g_acc + nbase)[q];
        float4 h;
        h.x = rsqrtf((float)(d.x + 1)) * a.x + b;
        h.y = rsqrtf((float)(d.y + 1)) * a.y + b;
        h.z = rsqrtf((float)(d.z + 1)) * a.z + b;
        h.w = rsqrtf((float)(d.w + 1)) * a.w + b;
        reinterpret_cast<float4*>(sh)[q] = h;
    }
    // Re-zero this block's exclusive g_deg range (coalesced, outside load chain).
    for (int q = threadIdx.x; q < NQ; q += FC_TPB)
        reinterpret_cast<int4*>(g_deg + nbase)[q] = make_int4(0, 0, 0, 0);
    __syncthreads();

    // Phase B: one thread per graph.
    if (threadIdx.x < FC_GRAPHS_PER_BLOCK) {
        int g = blockIdx.x * FC_GRAPHS_PER_BLOCK + threadIdx.x;
        const float* hh = sh + threadIdx.x * NODES_PER_GRAPH;
        float s0 = fc_b[0];
        float s1 = fc_b[1];
#pragma unroll
        for (int j = 0; j < NODES_PER_GRAPH; ++j) {
            float h = hh[j];
            s0 = fmaf(h, __ldg(&fc_w[j]), s0);
            s1 = fmaf(h, __ldg(&fc_w[NODES_PER_GRAPH + j]), s1);
        }
        reinterpret_cast<float2*>(out)[g] = make_float2(s0, s1);
    }
}

// ---------------------------------------------------------------------------
static void launch_pdl(void* func, dim3 grid, dim3 block,
                       void** args, bool pdl)
{
    cudaLaunchConfig_t cfg = {};
    cfg.gridDim  = grid;
    cfg.blockDim = block;
    cfg.stream   = 0;
    cudaLaunchAttribute attr[1];
    if (pdl) {
        attr[0].id = cudaLaunchAttributeProgrammaticStreamSerialization;
        attr[0].val.programmaticStreamSerializationAllowed = 1;
        cfg.attrs = attr;
        cfg.numAttrs = 1;
    }
    cudaLaunchKernelExC(&cfg, func, args);
}

extern "C" void kernel_launch(void* const* d_in, const int* in_sizes, int n_in,
                              void* d_out, int out_size)
{
    // Resolve inputs BY SIZE. Sizes: x=5,000,000; edge_index=160,000,000
    // (elements, dtype int32 or int64 — detected on device);
    // conv_w=1; conv_b=1 (in appearance order); fc_w=100; fc_b=2.
    const float* x      = nullptr;
    const void*  eidx   = nullptr;
    const float* conv_w = nullptr;
    const float* conv_b = nullptr;
    const float* fc_w   = nullptr;
    const float* fc_b   = nullptr;
    long long    n_edge_elems = 0;

    for (int i = 0; i < n_in; ++i) {
        long long s = in_sizes[i];
        if (s == 160000000LL)      { eidx = d_in[i]; n_edge_elems = s; }
        else if (s == 5000000LL)   { x    = (const float*)d_in[i]; }
        else if (s == 100LL)       { fc_w = (const float*)d_in[i]; }
        else if (s == 2LL)         { fc_b = (const float*)d_in[i]; }
        else if (s == 1LL) {
            if (!conv_w) conv_w = (const float*)d_in[i];
            else         conv_b = (const float*)d_in[i];
        }
    }

    float* out = (float*)d_out;
    long long E = n_edge_elems / 2;

    const long long* row64 = (const long long*)eidx;
    const long long* col64 = row64 + E;
    const int*       row32 = (const int*)eidx;
    const int*       col32 = row32 + E;
    const unsigned long long* ebase = (const unsigned long long*)eidx;

    const int TPB = 256;
    dim3 blk(TPB);
    dim3 prep_grid((NNODES / 4 + FC_TPB - 1) / FC_TPB);
    dim3 edge_grid((unsigned)((E + (long long)TPB * 4 - 1) / ((long long)TPB * 4)));
    dim3 fc_grid(NGRAPHS / FC_GRAPHS_PER_BLOCK);     // 1000 (exact)

    {   // k_count (no PDL — first kernel; g_deg zeroed by prior k_fc / load-init)
        void* args[] = {(void*)&col64, (void*)&col32, (void*)&ebase,
                        (void*)&x, (void*)&conv_w, (void*)&E};
        launch_pdl((void*)k_count, edge_grid, blk, args, false);
    }
    {   // k_prep (PDL)
        void* args[] = {};
        launch_pdl((void*)k_prep, prep_grid, dim3(FC_TPB), args, true);
    }
    {   // k_edge (PDL)
        void* args[] = {(void*)&row64, (void*)&col64, (void*)&row32,
                        (void*)&col32, (void*)&ebase, (void*)&E};
        launch_pdl((void*)k_edge, edge_grid, blk, args, true);
    }
    {   // k_fc (PDL)
        void* args[] = {(void*)&conv_b, (void*)&fc_w, (void*)&fc_b, (void*)&out};
        launch_pdl((void*)k_fc, fc_grid, dim3(FC_TPB), args, true);
    }
}